// round 9
// baseline (speedup 1.0000x reference)
#include <cuda_runtime.h>
#include <cuda_bf16.h>
#include <cstdint>

#define Bb 16
#define Cc 306
#define Tt 4096
#define Mm 270
#define Gg 64
#define CP 320            // padded channel count (5 chunks of 64)
#define MPAD 288          // 3 m-chunks of 96
#define TT 128            // t-tile per CTA
#define NTH 512

// ---------------- device scratch ----------------
__device__ __nv_bfloat16 d_Shi[Bb * Gg * CP];
__device__ __nv_bfloat16 d_Slo[Bb * Gg * CP];
__device__ __nv_bfloat16 d_Whi[MPAD * Gg];
__device__ __nv_bfloat16 d_Wlo[MPAD * Gg];

__device__ __forceinline__ uint32_t smem_u32(const void* p) {
    uint32_t a;
    asm("{ .reg .u64 t; cvta.to.shared.u64 t, %1; cvt.u32.u64 %0, t; }" : "=r"(a) : "l"(p));
    return a;
}
__device__ __forceinline__ void ldsm_x4(uint32_t* r, uint32_t addr) {
    asm volatile("ldmatrix.sync.aligned.m8n8.x4.shared.b16 {%0,%1,%2,%3}, [%4];"
                 : "=r"(r[0]), "=r"(r[1]), "=r"(r[2]), "=r"(r[3]) : "r"(addr));
}
__device__ __forceinline__ void ldsm_x4_t(uint32_t* r, uint32_t addr) {
    asm volatile("ldmatrix.sync.aligned.m8n8.x4.trans.shared.b16 {%0,%1,%2,%3}, [%4];"
                 : "=r"(r[0]), "=r"(r[1]), "=r"(r[2]), "=r"(r[3]) : "r"(addr));
}
__device__ __forceinline__ void mma16816(float* c, const uint32_t* a, const uint32_t* b) {
    asm volatile(
        "mma.sync.aligned.m16n8k16.row.col.f32.bf16.bf16.f32 "
        "{%0,%1,%2,%3}, {%4,%5,%6,%7}, {%8,%9}, {%0,%1,%2,%3};"
        : "+f"(c[0]), "+f"(c[1]), "+f"(c[2]), "+f"(c[3])
        : "r"(a[0]), "r"(a[1]), "r"(a[2]), "r"(a[3]), "r"(b[0]), "r"(b[1]));
}
__device__ __forceinline__ void cp16(uint32_t sm, const void* g) {
    asm volatile("cp.async.ca.shared.global [%0], [%1], 16;" :: "r"(sm), "l"(g));
}
#define CP_COMMIT() asm volatile("cp.async.commit_group;" ::: "memory")
#define CP_WAIT0()  asm volatile("cp.async.wait_group 0;" ::: "memory")

// ---------------- setup kernel (S build + W split, fused) ----------------
__global__ void setup_kernel(const float* __restrict__ pos, const float* __restrict__ W) {
    int i = blockIdx.x * 256 + threadIdx.x;
    if (i < Bb * Gg * CP) {
        int c = i % CP;
        int cell = (i / CP) % Gg;
        int b = i / (CP * Gg);
        float s = 0.0f;
        if (c < Cc) {
            float gp0 = (pos[(b * Cc + c) * 2 + 0] + 1.0f) * 4.0f;
            float gp1 = (pos[(b * Cc + c) * 2 + 1] + 1.0f) * 4.0f;
            float lo0 = floorf(gp0), lo1 = floorf(gp1);
            int il0 = min(7, max(0, (int)lo0)), il1 = min(7, max(0, (int)lo1));
            int ih0 = min(7, max(0, (int)ceilf(gp0))), ih1 = min(7, max(0, (int)ceilf(gp1)));
            float wh0 = gp0 - lo0, wl0 = 1.0f - wh0;
            float wh1 = gp1 - lo1, wl1 = 1.0f - wh1;
            if (il0 * 8 + il1 == cell) s += wl0 * wl1;
            if (il0 * 8 + ih1 == cell) s += wl0 * wh1;
            if (ih0 * 8 + il1 == cell) s += wh0 * wl1;
            if (ih0 * 8 + ih1 == cell) s += wh0 * wh1;
        }
        __nv_bfloat16 h = __float2bfloat16(s);
        d_Shi[i] = h;
        d_Slo[i] = __float2bfloat16(s - __bfloat162float(h));
    } else {
        int j = i - Bb * Gg * CP;
        if (j < MPAD * Gg) {
            float v = (j < Mm * Gg) ? W[j] : 0.0f;
            __nv_bfloat16 h = __float2bfloat16(v);
            d_Whi[j] = h;
            d_Wlo[j] = __float2bfloat16(v - __bfloat162float(h));
        }
    }
}

// ---------------- fused kernel: 512 threads, fine warp tiles ----------------
#define A1PITCH 72
#define B1PITCH 136
#define GPITCH  136
#define WPITCH  72
#define SM_A1(buf) ((buf) * 18432)            // AHI +0, ALO +9216
#define SM_B1(buf) (36864 + (buf) * 34816)    // BHI +0, BLO +17408
#define SM_GV      106496                     // GVHI +0, GVLO +17408
#define SM_W(buf)  ((buf) * 27648)            // WHI +0, WLO +13824 (overlays A1/B1)
#define SM_TOTAL   141312

__global__ void __launch_bounds__(NTH, 1)
fused_kernel(const float* __restrict__ x, float* __restrict__ out) {
    extern __shared__ char smem[];
    const uint32_t sb = smem_u32(smem);
    const int tid = threadIdx.x;
    const int wid = tid >> 5;           // 0..15
    const int lane = tid & 31;

    const int t0 = blockIdx.x * TT;
    const int b  = blockIdx.y;

    const int arow = lane & 15;
    const int acol = (lane >> 4) * 8;

    // ======== phase 1: gv[64 x 128] = S_b @ x_tile ========
    // 16 warps as 4m x 4t grid; warp tile 16m x 32t
    const int wm1 = wid >> 2;           // 0..3
    const int wt1 = wid & 3;            // 0..3

    float gacc[4][4];
#pragma unroll
    for (int j = 0; j < 4; j++)
#pragma unroll
        for (int q = 0; q < 4; q++) gacc[j][q] = 0.0f;

    float4 xv[4];
    auto load_X = [&](int c0) {   // c0 = channel offset
#pragma unroll
        for (int it = 0; it < 4; it++) {
            int cg = c0 + wid + 16 * it;
            xv[it] = (cg < Cc)
                ? *(const float4*)(x + ((size_t)(b * Cc + cg)) * Tt + t0 + lane * 4)
                : make_float4(0.f, 0.f, 0.f, 0.f);
        }
    };
    auto cpS = [&](int c0, int buf) {
        const __nv_bfloat16* baseHi = d_Shi + (size_t)b * Gg * CP + c0;
        const __nv_bfloat16* baseLo = d_Slo + (size_t)b * Gg * CP + c0;
        uint32_t smA = sb + SM_A1(buf);
#pragma unroll
        for (int it = 0; it < 2; it++) {
            int idx = tid + it * NTH;      // 0..1023
            int hl = idx >> 9;
            int r = (idx >> 3) & 63;
            int s = idx & 7;
            const __nv_bfloat16* g = (hl ? baseLo : baseHi) + r * CP + s * 8;
            cp16(smA + hl * 9216 + (r * A1PITCH + s * 8) * 2, g);
        }
    };
    auto stsX = [&](int buf) {
        char* base = smem + SM_B1(buf);
#pragma unroll
        for (int it = 0; it < 4; it++) {
            int r = wid + 16 * it;
            float4 v = xv[it];
            __nv_bfloat162 h0 = __floats2bfloat162_rn(v.x, v.y);
            __nv_bfloat162 h1 = __floats2bfloat162_rn(v.z, v.w);
            __nv_bfloat162 l0 = __floats2bfloat162_rn(
                v.x - __bfloat162float(__low2bfloat16(h0)),
                v.y - __bfloat162float(__high2bfloat16(h0)));
            __nv_bfloat162 l1 = __floats2bfloat162_rn(
                v.z - __bfloat162float(__low2bfloat16(h1)),
                v.w - __bfloat162float(__high2bfloat16(h1)));
            uint32_t boff = (r * B1PITCH + lane * 4) * 2;
            *(uint32_t*)(base + boff)             = *(uint32_t*)&h0;
            *(uint32_t*)(base + boff + 4)         = *(uint32_t*)&h1;
            *(uint32_t*)(base + 17408 + boff)     = *(uint32_t*)&l0;
            *(uint32_t*)(base + 17408 + boff + 4) = *(uint32_t*)&l1;
        }
    };
    auto mma1 = [&](int buf) {
        uint32_t baseA = sb + SM_A1(buf);
        uint32_t baseB = sb + SM_B1(buf);
#pragma unroll
        for (int ks = 0; ks < 4; ks++) {
            const int k0 = ks * 16;
            uint32_t ahi[4], alo[4];
            {
                uint32_t off = ((wm1 * 16 + arow) * A1PITCH + k0 + acol) * 2;
                ldsm_x4(ahi, baseA + off);
                ldsm_x4(alo, baseA + 9216 + off);
            }
#pragma unroll
            for (int j2 = 0; j2 < 2; j2++) {
                uint32_t off = ((k0 + arow) * B1PITCH + wt1 * 32 + j2 * 16 + acol) * 2;
                uint32_t bhi[4], blo[4];
                ldsm_x4_t(bhi, baseB + off);
                ldsm_x4_t(blo, baseB + 17408 + off);
#pragma unroll
                for (int jh = 0; jh < 2; jh++) {
                    int j = j2 * 2 + jh;
                    mma16816(gacc[j], ahi, &bhi[jh * 2]);
                    mma16816(gacc[j], ahi, &blo[jh * 2]);
                    mma16816(gacc[j], alo, &bhi[jh * 2]);
                }
            }
        }
    };

    // prologue: stage chunk 0, start LDG chunk 1
    cpS(0, 0); CP_COMMIT();
    load_X(0);
    stsX(0);
    load_X(64);
    CP_WAIT0();
    __syncthreads();

    for (int kc = 0; kc < 5; kc++) {
        const int cur = kc & 1, nxt = cur ^ 1;
        if (kc < 4) { cpS((kc + 1) * 64, nxt); CP_COMMIT(); }
        mma1(cur);
        if (kc < 4) {
            stsX(nxt);                             // x(kc+1): LDGs landed during MMA
            if (kc < 3) load_X((kc + 2) * 64);     // next LDGs fly under next MMA
            CP_WAIT0();
        }
        __syncthreads();
    }

    // ======== phase 2 prologue: W(0) cp.async overlapped with gv split ========
    auto cpW = [&](int m0, int buf) {
        uint32_t smW = sb + SM_W(buf);
#pragma unroll
        for (int it = 0; it < 3; it++) {
            int idx = tid + it * NTH;      // 0..1535
            int hl = idx >= 768;
            int j = hl ? idx - 768 : idx;
            int r = j >> 3;
            int s = j & 7;
            const __nv_bfloat16* g = (hl ? d_Wlo : d_Whi) + (m0 + r) * Gg + s * 8;
            cp16(smW + hl * 13824 + (r * WPITCH + s * 8) * 2, g);
        }
    };
    cpW(0, 0); CP_COMMIT();

    // gv split into region Y
    {
        int r0 = wm1 * 16 + (lane >> 2);
        int r1 = r0 + 8;
#pragma unroll
        for (int j = 0; j < 4; j++) {
            int t = wt1 * 32 + j * 8 + (lane & 3) * 2;
            __nv_bfloat162 h0 = __floats2bfloat162_rn(gacc[j][0], gacc[j][1]);
            __nv_bfloat162 l0 = __floats2bfloat162_rn(
                gacc[j][0] - __bfloat162float(__low2bfloat16(h0)),
                gacc[j][1] - __bfloat162float(__high2bfloat16(h0)));
            __nv_bfloat162 h1 = __floats2bfloat162_rn(gacc[j][2], gacc[j][3]);
            __nv_bfloat162 l1 = __floats2bfloat162_rn(
                gacc[j][2] - __bfloat162float(__low2bfloat16(h1)),
                gacc[j][3] - __bfloat162float(__high2bfloat16(h1)));
            *(uint32_t*)(smem + SM_GV + (r0 * GPITCH + t) * 2)         = *(uint32_t*)&h0;
            *(uint32_t*)(smem + SM_GV + 17408 + (r0 * GPITCH + t) * 2) = *(uint32_t*)&l0;
            *(uint32_t*)(smem + SM_GV + (r1 * GPITCH + t) * 2)         = *(uint32_t*)&h1;
            *(uint32_t*)(smem + SM_GV + 17408 + (r1 * GPITCH + t) * 2) = *(uint32_t*)&l1;
        }
    }
    CP_WAIT0();
    __syncthreads();

    // ======== phase 2: out = W_chunk @ gv, W double-buffered ========
    // 16 warps as 2m x 8t grid; warp tile 48m x 16t
    const int wm2 = wid >> 3;           // 0..1
    const int wt2 = wid & 7;            // 0..7

    for (int mc = 0; mc < 3; mc++) {
        const int cur = mc & 1, nxt = cur ^ 1;
        if (mc < 2) { cpW((mc + 1) * 96, nxt); CP_COMMIT(); }

        float acc[3][2][4];
#pragma unroll
        for (int i = 0; i < 3; i++)
#pragma unroll
            for (int j = 0; j < 2; j++)
#pragma unroll
                for (int q = 0; q < 4; q++) acc[i][j][q] = 0.0f;

        uint32_t baseW = sb + SM_W(cur);
#pragma unroll
        for (int ks = 0; ks < 4; ks++) {
            const int k0 = ks * 16;
            uint32_t ahi[3][4], alo[3][4];
#pragma unroll
            for (int i = 0; i < 3; i++) {
                uint32_t off = ((wm2 * 48 + i * 16 + arow) * WPITCH + k0 + acol) * 2;
                ldsm_x4(ahi[i], baseW + off);
                ldsm_x4(alo[i], baseW + 13824 + off);
            }
            uint32_t off = ((k0 + arow) * GPITCH + wt2 * 16 + acol) * 2;
            uint32_t bhi[4], blo[4];
            ldsm_x4_t(bhi, sb + SM_GV + off);
            ldsm_x4_t(blo, sb + SM_GV + 17408 + off);
#pragma unroll
            for (int j = 0; j < 2; j++) {
#pragma unroll
                for (int i = 0; i < 3; i++) {
                    mma16816(acc[i][j], ahi[i], &bhi[j * 2]);
                    mma16816(acc[i][j], ahi[i], &blo[j * 2]);
                    mma16816(acc[i][j], alo[i], &bhi[j * 2]);
                }
            }
        }

        // epilogue: store out chunk
        const int m0 = mc * 96;
#pragma unroll
        for (int i = 0; i < 3; i++) {
            int mlo = m0 + wm2 * 48 + i * 16 + (lane >> 2);
            int mhi = mlo + 8;
#pragma unroll
            for (int j = 0; j < 2; j++) {
                int t = t0 + wt2 * 16 + j * 8 + (lane & 3) * 2;
                if (mlo < Mm)
                    *(float2*)&out[((size_t)b * Mm + mlo) * Tt + t] =
                        make_float2(acc[i][j][0], acc[i][j][1]);
                if (mhi < Mm)
                    *(float2*)&out[((size_t)b * Mm + mhi) * Tt + t] =
                        make_float2(acc[i][j][2], acc[i][j][3]);
            }
        }
        if (mc < 2) {
            CP_WAIT0();
            __syncthreads();
        }
    }
}

// ---------------- launch ----------------
extern "C" void kernel_launch(void* const* d_in, const int* in_sizes, int n_in,
                              void* d_out, int out_size) {
    const float* x   = (const float*)d_in[0];  // [B, C, T]
    const float* pos = (const float*)d_in[1];  // [B, C, 2]
    const float* W   = (const float*)d_in[2];  // [M, G]
    float* out = (float*)d_out;                // [B, M, T]

    cudaFuncSetAttribute(fused_kernel, cudaFuncAttributeMaxDynamicSharedMemorySize, SM_TOTAL);

    const int njobs = Bb * Gg * CP + MPAD * Gg;
    setup_kernel<<<(njobs + 255) / 256, 256>>>(pos, W);
    fused_kernel<<<dim3(Tt / TT, Bb), NTH, SM_TOTAL>>>(x, out);
}

// round 10
// speedup vs baseline: 1.1180x; 1.1180x over previous
#include <cuda_runtime.h>
#include <cuda_bf16.h>
#include <cstdint>

#define Bb 16
#define Cc 306
#define Tt 4096
#define Mm 270
#define Gg 64
#define CP 320            // padded channel count (5 chunks of 64)
#define MPAD 288          // 3 m-chunks of 96
#define TT 128            // t-tile per CTA
#define NTH 256

// ---------------- device scratch ----------------
__device__ __nv_bfloat16 d_Shi[Bb * Gg * CP];
__device__ __nv_bfloat16 d_Slo[Bb * Gg * CP];
__device__ __nv_bfloat16 d_Whi[MPAD * Gg];
__device__ __nv_bfloat16 d_Wlo[MPAD * Gg];

__device__ __forceinline__ uint32_t smem_u32(const void* p) {
    uint32_t a;
    asm("{ .reg .u64 t; cvta.to.shared.u64 t, %1; cvt.u32.u64 %0, t; }" : "=r"(a) : "l"(p));
    return a;
}
__device__ __forceinline__ void ldsm_x4(uint32_t* r, uint32_t addr) {
    asm volatile("ldmatrix.sync.aligned.m8n8.x4.shared.b16 {%0,%1,%2,%3}, [%4];"
                 : "=r"(r[0]), "=r"(r[1]), "=r"(r[2]), "=r"(r[3]) : "r"(addr));
}
__device__ __forceinline__ void ldsm_x4_t(uint32_t* r, uint32_t addr) {
    asm volatile("ldmatrix.sync.aligned.m8n8.x4.trans.shared.b16 {%0,%1,%2,%3}, [%4];"
                 : "=r"(r[0]), "=r"(r[1]), "=r"(r[2]), "=r"(r[3]) : "r"(addr));
}
__device__ __forceinline__ void mma16816(float* c, const uint32_t* a, const uint32_t* b) {
    asm volatile(
        "mma.sync.aligned.m16n8k16.row.col.f32.bf16.bf16.f32 "
        "{%0,%1,%2,%3}, {%4,%5,%6,%7}, {%8,%9}, {%0,%1,%2,%3};"
        : "+f"(c[0]), "+f"(c[1]), "+f"(c[2]), "+f"(c[3])
        : "r"(a[0]), "r"(a[1]), "r"(a[2]), "r"(a[3]), "r"(b[0]), "r"(b[1]));
}
__device__ __forceinline__ void cp16(uint32_t sm, const void* g) {
    asm volatile("cp.async.ca.shared.global [%0], [%1], 16;" :: "r"(sm), "l"(g));
}
#define CP_COMMIT() asm volatile("cp.async.commit_group;" ::: "memory")
#define CP_WAIT0()  asm volatile("cp.async.wait_group 0;" ::: "memory")

// ---------------- setup kernel (S build + W split, fused) ----------------
__global__ void setup_kernel(const float* __restrict__ pos, const float* __restrict__ W) {
    int i = blockIdx.x * 256 + threadIdx.x;
    if (i < Bb * Gg * CP) {
        int c = i % CP;
        int cell = (i / CP) % Gg;
        int b = i / (CP * Gg);
        float s = 0.0f;
        if (c < Cc) {
            float gp0 = (pos[(b * Cc + c) * 2 + 0] + 1.0f) * 4.0f;
            float gp1 = (pos[(b * Cc + c) * 2 + 1] + 1.0f) * 4.0f;
            float lo0 = floorf(gp0), lo1 = floorf(gp1);
            int il0 = min(7, max(0, (int)lo0)), il1 = min(7, max(0, (int)lo1));
            int ih0 = min(7, max(0, (int)ceilf(gp0))), ih1 = min(7, max(0, (int)ceilf(gp1)));
            float wh0 = gp0 - lo0, wl0 = 1.0f - wh0;
            float wh1 = gp1 - lo1, wl1 = 1.0f - wh1;
            if (il0 * 8 + il1 == cell) s += wl0 * wl1;
            if (il0 * 8 + ih1 == cell) s += wl0 * wh1;
            if (ih0 * 8 + il1 == cell) s += wh0 * wl1;
            if (ih0 * 8 + ih1 == cell) s += wh0 * wh1;
        }
        __nv_bfloat16 h = __float2bfloat16(s);
        d_Shi[i] = h;
        d_Slo[i] = __float2bfloat16(s - __bfloat162float(h));
    } else {
        int j = i - Bb * Gg * CP;
        if (j < MPAD * Gg) {
            float v = (j < Mm * Gg) ? W[j] : 0.0f;
            __nv_bfloat16 h = __float2bfloat16(v);
            d_Whi[j] = h;
            d_Wlo[j] = __float2bfloat16(v - __bfloat162float(h));
        }
    }
}

// ---------------- fused kernel: single-buffer, 2 CTAs/SM ----------------
#define A1PITCH 72
#define B1PITCH 136
#define GPITCH  136
#define WPITCH  72
#define SM_A1   0                 // AHI +0, ALO +9216  (ends 18432)
#define SM_B1   18432             // BHI +0, BLO +17408 (ends 53248)
#define SM_GV   53248             // GVHI +0, GVLO +17408 (ends 88064)
#define SM_W    0                 // WHI +0, WLO +13824 (overlay on A1/B1, ends 27648)
#define SM_TOTAL 88064

__global__ void __launch_bounds__(NTH, 2)
fused_kernel(const float* __restrict__ x, float* __restrict__ out) {
    extern __shared__ char smem[];
    const uint32_t sb = smem_u32(smem);
    const int tid = threadIdx.x;
    const int wid = tid >> 5;           // 0..7
    const int lane = tid & 31;

    const int t0 = blockIdx.x * TT;
    const int b  = blockIdx.y;

    const int arow = lane & 15;
    const int acol = (lane >> 4) * 8;

    // ======== phase 1: gv[64 x 128] = S_b @ x_tile ========
    // 8 warps as 2m x 4t; warp tile 32m x 32t
    const int wm1 = wid >> 2;
    const int wt1 = wid & 3;

    float gacc[2][4][4];
#pragma unroll
    for (int i = 0; i < 2; i++)
#pragma unroll
        for (int j = 0; j < 4; j++)
#pragma unroll
            for (int q = 0; q < 4; q++) gacc[i][j][q] = 0.0f;

    float4 xv[8];
    auto load_X = [&](int c0) {   // c0 = channel offset
#pragma unroll
        for (int it = 0; it < 8; it++) {
            int cg = c0 + wid + 8 * it;
            xv[it] = (cg < Cc)
                ? *(const float4*)(x + ((size_t)(b * Cc + cg)) * Tt + t0 + lane * 4)
                : make_float4(0.f, 0.f, 0.f, 0.f);
        }
    };
    auto cpS = [&](int c0) {
        const __nv_bfloat16* baseHi = d_Shi + (size_t)b * Gg * CP + c0;
        const __nv_bfloat16* baseLo = d_Slo + (size_t)b * Gg * CP + c0;
        uint32_t smA = sb + SM_A1;
#pragma unroll
        for (int it = 0; it < 4; it++) {
            int idx = tid + it * NTH;      // 0..1023
            int hl = idx >> 9;
            int r = (idx >> 3) & 63;
            int s = idx & 7;
            const __nv_bfloat16* g = (hl ? baseLo : baseHi) + r * CP + s * 8;
            cp16(smA + hl * 9216 + (r * A1PITCH + s * 8) * 2, g);
        }
    };
    auto stsX = [&]() {
        char* base = smem + SM_B1;
#pragma unroll
        for (int it = 0; it < 8; it++) {
            int r = wid + 8 * it;
            float4 v = xv[it];
            __nv_bfloat162 h0 = __floats2bfloat162_rn(v.x, v.y);
            __nv_bfloat162 h1 = __floats2bfloat162_rn(v.z, v.w);
            __nv_bfloat162 l0 = __floats2bfloat162_rn(
                v.x - __bfloat162float(__low2bfloat16(h0)),
                v.y - __bfloat162float(__high2bfloat16(h0)));
            __nv_bfloat162 l1 = __floats2bfloat162_rn(
                v.z - __bfloat162float(__low2bfloat16(h1)),
                v.w - __bfloat162float(__high2bfloat16(h1)));
            uint32_t boff = (r * B1PITCH + lane * 4) * 2;
            *(uint32_t*)(base + boff)             = *(uint32_t*)&h0;
            *(uint32_t*)(base + boff + 4)         = *(uint32_t*)&h1;
            *(uint32_t*)(base + 17408 + boff)     = *(uint32_t*)&l0;
            *(uint32_t*)(base + 17408 + boff + 4) = *(uint32_t*)&l1;
        }
    };
    auto mma1 = [&]() {
        uint32_t baseA = sb + SM_A1;
        uint32_t baseB = sb + SM_B1;
#pragma unroll
        for (int ks = 0; ks < 4; ks++) {
            const int k0 = ks * 16;
            uint32_t ahi[2][4], alo[2][4];
#pragma unroll
            for (int i = 0; i < 2; i++) {
                uint32_t off = ((wm1 * 32 + i * 16 + arow) * A1PITCH + k0 + acol) * 2;
                ldsm_x4(ahi[i], baseA + off);
                ldsm_x4(alo[i], baseA + 9216 + off);
            }
#pragma unroll
            for (int j2 = 0; j2 < 2; j2++) {
                uint32_t off = ((k0 + arow) * B1PITCH + wt1 * 32 + j2 * 16 + acol) * 2;
                uint32_t bhi[4], blo[4];
                ldsm_x4_t(bhi, baseB + off);
                ldsm_x4_t(blo, baseB + 17408 + off);
#pragma unroll
                for (int jh = 0; jh < 2; jh++) {
                    int j = j2 * 2 + jh;
#pragma unroll
                    for (int i = 0; i < 2; i++) {
                        mma16816(gacc[i][j], ahi[i], &bhi[jh * 2]);
                        mma16816(gacc[i][j], ahi[i], &blo[jh * 2]);
                        mma16816(gacc[i][j], alo[i], &bhi[jh * 2]);
                    }
                }
            }
        }
    };

    // prologue: stage chunk 0, prefetch x chunk 1
    cpS(0); CP_COMMIT();
    load_X(0);
    stsX();
    load_X(64);
    CP_WAIT0();
    __syncthreads();

    for (int kc = 0; kc < 5; kc++) {
        mma1();
        if (kc < 4) {
            __syncthreads();                       // ldsm of chunk kc done
            cpS((kc + 1) * 64); CP_COMMIT();
            stsX();                                // x(kc+1) from regs
            if (kc < 3) load_X((kc + 2) * 64);     // flies under next MMA
            CP_WAIT0();
            __syncthreads();
        }
    }
    __syncthreads();                               // last mma1 ldsm done before W overlay

    // ======== phase 2 prologue: W(0) cp.async overlapped with gv split ========
    auto cpW = [&](int m0) {
        uint32_t smW = sb + SM_W;
#pragma unroll
        for (int it = 0; it < 6; it++) {
            int idx = tid + it * NTH;      // 0..1535
            int hl = idx >= 768;
            int j = hl ? idx - 768 : idx;
            int r = j >> 3;
            int s = j & 7;
            const __nv_bfloat16* g = (hl ? d_Wlo : d_Whi) + (m0 + r) * Gg + s * 8;
            cp16(smW + hl * 13824 + (r * WPITCH + s * 8) * 2, g);
        }
    };
    cpW(0); CP_COMMIT();

    // gv split into region Y
#pragma unroll
    for (int i = 0; i < 2; i++) {
        int r0 = wm1 * 32 + i * 16 + (lane >> 2);
        int r1 = r0 + 8;
#pragma unroll
        for (int j = 0; j < 4; j++) {
            int t = wt1 * 32 + j * 8 + (lane & 3) * 2;
            __nv_bfloat162 h0 = __floats2bfloat162_rn(gacc[i][j][0], gacc[i][j][1]);
            __nv_bfloat162 l0 = __floats2bfloat162_rn(
                gacc[i][j][0] - __bfloat162float(__low2bfloat16(h0)),
                gacc[i][j][1] - __bfloat162float(__high2bfloat16(h0)));
            __nv_bfloat162 h1 = __floats2bfloat162_rn(gacc[i][j][2], gacc[i][j][3]);
            __nv_bfloat162 l1 = __floats2bfloat162_rn(
                gacc[i][j][2] - __bfloat162float(__low2bfloat16(h1)),
                gacc[i][j][3] - __bfloat162float(__high2bfloat16(h1)));
            *(uint32_t*)(smem + SM_GV + (r0 * GPITCH + t) * 2)         = *(uint32_t*)&h0;
            *(uint32_t*)(smem + SM_GV + 17408 + (r0 * GPITCH + t) * 2) = *(uint32_t*)&l0;
            *(uint32_t*)(smem + SM_GV + (r1 * GPITCH + t) * 2)         = *(uint32_t*)&h1;
            *(uint32_t*)(smem + SM_GV + 17408 + (r1 * GPITCH + t) * 2) = *(uint32_t*)&l1;
        }
    }
    CP_WAIT0();
    __syncthreads();

    // ======== phase 2: out = W_chunk @ gv, single-buffered W ========
    // 8 warps as 2m x 4t; warp tile 48m x 32t
    const int wm2 = wid >> 2;
    const int wt2 = wid & 3;

    for (int mc = 0; mc < 3; mc++) {
        float acc[3][4][4];
#pragma unroll
        for (int i = 0; i < 3; i++)
#pragma unroll
            for (int j = 0; j < 4; j++)
#pragma unroll
                for (int q = 0; q < 4; q++) acc[i][j][q] = 0.0f;

        uint32_t baseW = sb + SM_W;
#pragma unroll
        for (int ks = 0; ks < 4; ks++) {
            const int k0 = ks * 16;
            uint32_t ahi[3][4], alo[3][4];
#pragma unroll
            for (int i = 0; i < 3; i++) {
                uint32_t off = ((wm2 * 48 + i * 16 + arow) * WPITCH + k0 + acol) * 2;
                ldsm_x4(ahi[i], baseW + off);
                ldsm_x4(alo[i], baseW + 13824 + off);
            }
#pragma unroll
            for (int j2 = 0; j2 < 2; j2++) {
                uint32_t off = ((k0 + arow) * GPITCH + wt2 * 32 + j2 * 16 + acol) * 2;
                uint32_t bhi[4], blo[4];
                ldsm_x4_t(bhi, sb + SM_GV + off);
                ldsm_x4_t(blo, sb + SM_GV + 17408 + off);
#pragma unroll
                for (int jh = 0; jh < 2; jh++) {
                    int j = j2 * 2 + jh;
#pragma unroll
                    for (int i = 0; i < 3; i++) {
                        mma16816(acc[i][j], ahi[i], &bhi[jh * 2]);
                        mma16816(acc[i][j], ahi[i], &blo[jh * 2]);
                        mma16816(acc[i][j], alo[i], &bhi[jh * 2]);
                    }
                }
            }
        }

        // stage next W chunk (after ldsm done), overlapped with epilogue STGs
        if (mc < 2) {
            __syncthreads();
            cpW((mc + 1) * 96); CP_COMMIT();
        }

        // epilogue: store out chunk
        const int m0 = mc * 96;
#pragma unroll
        for (int i = 0; i < 3; i++) {
            int mlo = m0 + wm2 * 48 + i * 16 + (lane >> 2);
            int mhi = mlo + 8;
#pragma unroll
            for (int j = 0; j < 4; j++) {
                int t = t0 + wt2 * 32 + j * 8 + (lane & 3) * 2;
                if (mlo < Mm)
                    *(float2*)&out[((size_t)b * Mm + mlo) * Tt + t] =
                        make_float2(acc[i][j][0], acc[i][j][1]);
                if (mhi < Mm)
                    *(float2*)&out[((size_t)b * Mm + mhi) * Tt + t] =
                        make_float2(acc[i][j][2], acc[i][j][3]);
            }
        }
        if (mc < 2) {
            CP_WAIT0();
            __syncthreads();
        }
    }
}

// ---------------- launch ----------------
extern "C" void kernel_launch(void* const* d_in, const int* in_sizes, int n_in,
                              void* d_out, int out_size) {
    const float* x   = (const float*)d_in[0];  // [B, C, T]
    const float* pos = (const float*)d_in[1];  // [B, C, 2]
    const float* W   = (const float*)d_in[2];  // [M, G]
    float* out = (float*)d_out;                // [B, M, T]

    cudaFuncSetAttribute(fused_kernel, cudaFuncAttributeMaxDynamicSharedMemorySize, SM_TOTAL);

    const int njobs = Bb * Gg * CP + MPAD * Gg;
    setup_kernel<<<(njobs + 255) / 256, 256>>>(pos, W);
    fused_kernel<<<dim3(Tt / TT, Bb), NTH, SM_TOTAL>>>(x, out);
}

// round 11
// speedup vs baseline: 1.1197x; 1.0015x over previous
#include <cuda_runtime.h>
#include <cuda_bf16.h>
#include <cstdint>

#define Bb 16
#define Cc 306
#define Tt 4096
#define Mm 270
#define Gg 64
#define CP 320            // padded channel count (5 chunks of 64)
#define MPAD 288          // 3 m-chunks of 96
#define TT 128            // t-tile per CTA
#define NTH 256

// ---------------- device scratch ----------------
__device__ __nv_bfloat16 d_Shi[Bb * Gg * CP];
__device__ __nv_bfloat16 d_Slo[Bb * Gg * CP];
__device__ __nv_bfloat16 d_Whi[MPAD * Gg];
__device__ __nv_bfloat16 d_Wlo[MPAD * Gg];

__device__ __forceinline__ uint32_t smem_u32(const void* p) {
    uint32_t a;
    asm("{ .reg .u64 t; cvta.to.shared.u64 t, %1; cvt.u32.u64 %0, t; }" : "=r"(a) : "l"(p));
    return a;
}
__device__ __forceinline__ void ldsm_x4(uint32_t* r, uint32_t addr) {
    asm volatile("ldmatrix.sync.aligned.m8n8.x4.shared.b16 {%0,%1,%2,%3}, [%4];"
                 : "=r"(r[0]), "=r"(r[1]), "=r"(r[2]), "=r"(r[3]) : "r"(addr));
}
__device__ __forceinline__ void ldsm_x4_t(uint32_t* r, uint32_t addr) {
    asm volatile("ldmatrix.sync.aligned.m8n8.x4.trans.shared.b16 {%0,%1,%2,%3}, [%4];"
                 : "=r"(r[0]), "=r"(r[1]), "=r"(r[2]), "=r"(r[3]) : "r"(addr));
}
__device__ __forceinline__ void mma16816(float* c, const uint32_t* a, const uint32_t* b) {
    asm volatile(
        "mma.sync.aligned.m16n8k16.row.col.f32.bf16.bf16.f32 "
        "{%0,%1,%2,%3}, {%4,%5,%6,%7}, {%8,%9}, {%0,%1,%2,%3};"
        : "+f"(c[0]), "+f"(c[1]), "+f"(c[2]), "+f"(c[3])
        : "r"(a[0]), "r"(a[1]), "r"(a[2]), "r"(a[3]), "r"(b[0]), "r"(b[1]));
}
__device__ __forceinline__ void cp16(uint32_t sm, const void* g) {
    asm volatile("cp.async.ca.shared.global [%0], [%1], 16;" :: "r"(sm), "l"(g));
}
#define CP_COMMIT() asm volatile("cp.async.commit_group;" ::: "memory")
#define CP_WAIT0()  asm volatile("cp.async.wait_group 0;" ::: "memory")

// ---------------- setup kernel (S build + W split, fused) ----------------
__global__ void setup_kernel(const float* __restrict__ pos, const float* __restrict__ W) {
    int i = blockIdx.x * 256 + threadIdx.x;
    if (i < Bb * Gg * CP) {
        int c = i % CP;
        int cell = (i / CP) % Gg;
        int b = i / (CP * Gg);
        float s = 0.0f;
        if (c < Cc) {
            float gp0 = (pos[(b * Cc + c) * 2 + 0] + 1.0f) * 4.0f;
            float gp1 = (pos[(b * Cc + c) * 2 + 1] + 1.0f) * 4.0f;
            float lo0 = floorf(gp0), lo1 = floorf(gp1);
            int il0 = min(7, max(0, (int)lo0)), il1 = min(7, max(0, (int)lo1));
            int ih0 = min(7, max(0, (int)ceilf(gp0))), ih1 = min(7, max(0, (int)ceilf(gp1)));
            float wh0 = gp0 - lo0, wl0 = 1.0f - wh0;
            float wh1 = gp1 - lo1, wl1 = 1.0f - wh1;
            if (il0 * 8 + il1 == cell) s += wl0 * wl1;
            if (il0 * 8 + ih1 == cell) s += wl0 * wh1;
            if (ih0 * 8 + il1 == cell) s += wh0 * wl1;
            if (ih0 * 8 + ih1 == cell) s += wh0 * wh1;
        }
        __nv_bfloat16 h = __float2bfloat16(s);
        d_Shi[i] = h;
        d_Slo[i] = __float2bfloat16(s - __bfloat162float(h));
    } else {
        int j = i - Bb * Gg * CP;
        if (j < MPAD * Gg) {
            float v = (j < Mm * Gg) ? W[j] : 0.0f;
            __nv_bfloat16 h = __float2bfloat16(v);
            d_Whi[j] = h;
            d_Wlo[j] = __float2bfloat16(v - __bfloat162float(h));
        }
    }
}

// ---------------- fused kernel: single-buffer, 2 CTAs/SM ----------------
#define A1PITCH 72
#define B1PITCH 136
#define GPITCH  136
#define WPITCH  72
#define SM_A1   0                 // AHI +0, ALO +9216  (ends 18432)
#define SM_B1   18432             // BHI +0, BLO +17408 (ends 53248)
#define SM_GV   53248             // GVHI +0, GVLO +17408 (ends 88064)
#define SM_W    0                 // WHI +0, WLO +13824 (overlay on A1/B1, ends 27648)
#define SM_TOTAL 88064

__global__ void __launch_bounds__(NTH, 2)
fused_kernel(const float* __restrict__ x, float* __restrict__ out) {
    extern __shared__ char smem[];
    const uint32_t sb = smem_u32(smem);
    const int tid = threadIdx.x;
    const int wid = tid >> 5;           // 0..7
    const int lane = tid & 31;

    const int t0 = blockIdx.x * TT;
    const int b  = blockIdx.y;

    const int arow = lane & 15;
    const int acol = (lane >> 4) * 8;

    // ======== phase 1: gv[64 x 128] = S_b @ x_tile ========
    // 8 warps as 2m x 4t; warp tile 32m x 32t
    const int wm1 = wid >> 2;
    const int wt1 = wid & 3;

    float gacc[2][4][4];
#pragma unroll
    for (int i = 0; i < 2; i++)
#pragma unroll
        for (int j = 0; j < 4; j++)
#pragma unroll
            for (int q = 0; q < 4; q++) gacc[i][j][q] = 0.0f;

    float4 xv[8];
    auto load_X = [&](int c0) {   // c0 = channel offset
#pragma unroll
        for (int it = 0; it < 8; it++) {
            int cg = c0 + wid + 8 * it;
            xv[it] = (cg < Cc)
                ? *(const float4*)(x + ((size_t)(b * Cc + cg)) * Tt + t0 + lane * 4)
                : make_float4(0.f, 0.f, 0.f, 0.f);
        }
    };
    auto cpS = [&](int c0) {
        const __nv_bfloat16* baseHi = d_Shi + (size_t)b * Gg * CP + c0;
        const __nv_bfloat16* baseLo = d_Slo + (size_t)b * Gg * CP + c0;
        uint32_t smA = sb + SM_A1;
#pragma unroll
        for (int it = 0; it < 4; it++) {
            int idx = tid + it * NTH;      // 0..1023
            int hl = idx >> 9;
            int r = (idx >> 3) & 63;
            int s = idx & 7;
            const __nv_bfloat16* g = (hl ? baseLo : baseHi) + r * CP + s * 8;
            cp16(smA + hl * 9216 + (r * A1PITCH + s * 8) * 2, g);
        }
    };
    auto stsX = [&]() {
        char* base = smem + SM_B1;
#pragma unroll
        for (int it = 0; it < 8; it++) {
            int r = wid + 8 * it;
            float4 v = xv[it];
            __nv_bfloat162 h0 = __floats2bfloat162_rn(v.x, v.y);
            __nv_bfloat162 h1 = __floats2bfloat162_rn(v.z, v.w);
            __nv_bfloat162 l0 = __floats2bfloat162_rn(
                v.x - __bfloat162float(__low2bfloat16(h0)),
                v.y - __bfloat162float(__high2bfloat16(h0)));
            __nv_bfloat162 l1 = __floats2bfloat162_rn(
                v.z - __bfloat162float(__low2bfloat16(h1)),
                v.w - __bfloat162float(__high2bfloat16(h1)));
            uint32_t boff = (r * B1PITCH + lane * 4) * 2;
            *(uint32_t*)(base + boff)             = *(uint32_t*)&h0;
            *(uint32_t*)(base + boff + 4)         = *(uint32_t*)&h1;
            *(uint32_t*)(base + 17408 + boff)     = *(uint32_t*)&l0;
            *(uint32_t*)(base + 17408 + boff + 4) = *(uint32_t*)&l1;
        }
    };
    auto mma1 = [&]() {
        uint32_t baseA = sb + SM_A1;
        uint32_t baseB = sb + SM_B1;
#pragma unroll
        for (int ks = 0; ks < 4; ks++) {
            const int k0 = ks * 16;
            uint32_t ahi[2][4], alo[2][4];
#pragma unroll
            for (int i = 0; i < 2; i++) {
                uint32_t off = ((wm1 * 32 + i * 16 + arow) * A1PITCH + k0 + acol) * 2;
                ldsm_x4(ahi[i], baseA + off);
                ldsm_x4(alo[i], baseA + 9216 + off);
            }
#pragma unroll
            for (int j2 = 0; j2 < 2; j2++) {
                uint32_t off = ((k0 + arow) * B1PITCH + wt1 * 32 + j2 * 16 + acol) * 2;
                uint32_t bhi[4], blo[4];
                ldsm_x4_t(bhi, baseB + off);
                ldsm_x4_t(blo, baseB + 17408 + off);
#pragma unroll
                for (int jh = 0; jh < 2; jh++) {
                    int j = j2 * 2 + jh;
#pragma unroll
                    for (int i = 0; i < 2; i++) {
                        mma16816(gacc[i][j], ahi[i], &bhi[jh * 2]);
                        mma16816(gacc[i][j], ahi[i], &blo[jh * 2]);
                        mma16816(gacc[i][j], alo[i], &bhi[jh * 2]);
                    }
                }
            }
        }
    };

    // prologue: stage chunk 0, prefetch x chunk 1
    cpS(0); CP_COMMIT();
    load_X(0);
    stsX();
    load_X(64);
    CP_WAIT0();
    __syncthreads();

    for (int kc = 0; kc < 5; kc++) {
        mma1();
        if (kc < 4) {
            __syncthreads();                       // ldsm of chunk kc done
            cpS((kc + 1) * 64); CP_COMMIT();
            stsX();                                // x(kc+1) from regs
            if (kc < 3) load_X((kc + 2) * 64);     // flies under next MMA
            CP_WAIT0();
            __syncthreads();
        }
    }
    __syncthreads();                               // last mma1 ldsm done before W overlay

    // ======== phase 2 prologue: W(0) cp.async overlapped with gv split ========
    auto cpW = [&](int m0) {
        uint32_t smW = sb + SM_W;
#pragma unroll
        for (int it = 0; it < 6; it++) {
            int idx = tid + it * NTH;      // 0..1535
            int hl = idx >= 768;
            int j = hl ? idx - 768 : idx;
            int r = j >> 3;
            int s = j & 7;
            const __nv_bfloat16* g = (hl ? d_Wlo : d_Whi) + (m0 + r) * Gg + s * 8;
            cp16(smW + hl * 13824 + (r * WPITCH + s * 8) * 2, g);
        }
    };
    cpW(0); CP_COMMIT();

    // gv split into region Y
#pragma unroll
    for (int i = 0; i < 2; i++) {
        int r0 = wm1 * 32 + i * 16 + (lane >> 2);
        int r1 = r0 + 8;
#pragma unroll
        for (int j = 0; j < 4; j++) {
            int t = wt1 * 32 + j * 8 + (lane & 3) * 2;
            __nv_bfloat162 h0 = __floats2bfloat162_rn(gacc[i][j][0], gacc[i][j][1]);
            __nv_bfloat162 l0 = __floats2bfloat162_rn(
                gacc[i][j][0] - __bfloat162float(__low2bfloat16(h0)),
                gacc[i][j][1] - __bfloat162float(__high2bfloat16(h0)));
            __nv_bfloat162 h1 = __floats2bfloat162_rn(gacc[i][j][2], gacc[i][j][3]);
            __nv_bfloat162 l1 = __floats2bfloat162_rn(
                gacc[i][j][2] - __bfloat162float(__low2bfloat16(h1)),
                gacc[i][j][3] - __bfloat162float(__high2bfloat16(h1)));
            *(uint32_t*)(smem + SM_GV + (r0 * GPITCH + t) * 2)         = *(uint32_t*)&h0;
            *(uint32_t*)(smem + SM_GV + 17408 + (r0 * GPITCH + t) * 2) = *(uint32_t*)&l0;
            *(uint32_t*)(smem + SM_GV + (r1 * GPITCH + t) * 2)         = *(uint32_t*)&h1;
            *(uint32_t*)(smem + SM_GV + 17408 + (r1 * GPITCH + t) * 2) = *(uint32_t*)&l1;
        }
    }
    CP_WAIT0();
    __syncthreads();

    // ======== phase 2: out = W_chunk @ gv, single-buffered W ========
    // 8 warps as 2m x 4t; warp tile 48m x 32t
    const int wm2 = wid >> 2;
    const int wt2 = wid & 3;

    for (int mc = 0; mc < 3; mc++) {
        float acc[3][4][4];
#pragma unroll
        for (int i = 0; i < 3; i++)
#pragma unroll
            for (int j = 0; j < 4; j++)
#pragma unroll
                for (int q = 0; q < 4; q++) acc[i][j][q] = 0.0f;

        uint32_t baseW = sb + SM_W;
#pragma unroll
        for (int ks = 0; ks < 4; ks++) {
            const int k0 = ks * 16;
            uint32_t ahi[3][4], alo[3][4];
#pragma unroll
            for (int i = 0; i < 3; i++) {
                uint32_t off = ((wm2 * 48 + i * 16 + arow) * WPITCH + k0 + acol) * 2;
                ldsm_x4(ahi[i], baseW + off);
                ldsm_x4(alo[i], baseW + 13824 + off);
            }
#pragma unroll
            for (int j2 = 0; j2 < 2; j2++) {
                uint32_t off = ((k0 + arow) * GPITCH + wt2 * 32 + j2 * 16 + acol) * 2;
                uint32_t bhi[4], blo[4];
                ldsm_x4_t(bhi, sb + SM_GV + off);
                ldsm_x4_t(blo, sb + SM_GV + 17408 + off);
#pragma unroll
                for (int jh = 0; jh < 2; jh++) {
                    int j = j2 * 2 + jh;
#pragma unroll
                    for (int i = 0; i < 3; i++) {
                        mma16816(acc[i][j], ahi[i], &bhi[jh * 2]);
                        mma16816(acc[i][j], ahi[i], &blo[jh * 2]);
                        mma16816(acc[i][j], alo[i], &bhi[jh * 2]);
                    }
                }
            }
        }

        // stage next W chunk (after ldsm done), overlapped with epilogue STGs
        if (mc < 2) {
            __syncthreads();
            cpW((mc + 1) * 96); CP_COMMIT();
        }

        // epilogue: store out chunk
        const int m0 = mc * 96;
#pragma unroll
        for (int i = 0; i < 3; i++) {
            int mlo = m0 + wm2 * 48 + i * 16 + (lane >> 2);
            int mhi = mlo + 8;
#pragma unroll
            for (int j = 0; j < 4; j++) {
                int t = t0 + wt2 * 32 + j * 8 + (lane & 3) * 2;
                if (mlo < Mm)
                    *(float2*)&out[((size_t)b * Mm + mlo) * Tt + t] =
                        make_float2(acc[i][j][0], acc[i][j][1]);
                if (mhi < Mm)
                    *(float2*)&out[((size_t)b * Mm + mhi) * Tt + t] =
                        make_float2(acc[i][j][2], acc[i][j][3]);
            }
        }
        if (mc < 2) {
            CP_WAIT0();
            __syncthreads();
        }
    }
}

// ---------------- launch ----------------
extern "C" void kernel_launch(void* const* d_in, const int* in_sizes, int n_in,
                              void* d_out, int out_size) {
    const float* x   = (const float*)d_in[0];  // [B, C, T]
    const float* pos = (const float*)d_in[1];  // [B, C, 2]
    const float* W   = (const float*)d_in[2];  // [M, G]
    float* out = (float*)d_out;                // [B, M, T]

    cudaFuncSetAttribute(fused_kernel, cudaFuncAttributeMaxDynamicSharedMemorySize, SM_TOTAL);

    const int njobs = Bb * Gg * CP + MPAD * Gg;
    setup_kernel<<<(njobs + 255) / 256, 256>>>(pos, W);
    fused_kernel<<<dim3(Tt / TT, Bb), NTH, SM_TOTAL>>>(x, out);
}

// round 12
// speedup vs baseline: 1.4587x; 1.3028x over previous
#include <cuda_runtime.h>
#include <cuda_fp16.h>
#include <cstdint>

#define Bb 16
#define Cc 306
#define Tt 4096
#define Mm 270
#define Gg 64
#define CP 320            // padded channel count (5 chunks of 64)
#define MPAD 288          // 3 m-chunks of 96
#define TT 128            // t-tile per CTA
#define NTH 256

// ---------------- device scratch (fp16, 16B-aligned for cp.async) ----------------
__device__ __align__(16) __half d_Sh[Bb * Gg * CP];
__device__ __align__(16) __half d_Wh[MPAD * Gg];

__device__ __forceinline__ uint32_t smem_u32(const void* p) {
    uint32_t a;
    asm("{ .reg .u64 t; cvta.to.shared.u64 t, %1; cvt.u32.u64 %0, t; }" : "=r"(a) : "l"(p));
    return a;
}
__device__ __forceinline__ void ldsm_x4(uint32_t* r, uint32_t addr) {
    asm volatile("ldmatrix.sync.aligned.m8n8.x4.shared.b16 {%0,%1,%2,%3}, [%4];"
                 : "=r"(r[0]), "=r"(r[1]), "=r"(r[2]), "=r"(r[3]) : "r"(addr));
}
__device__ __forceinline__ void ldsm_x4_t(uint32_t* r, uint32_t addr) {
    asm volatile("ldmatrix.sync.aligned.m8n8.x4.trans.shared.b16 {%0,%1,%2,%3}, [%4];"
                 : "=r"(r[0]), "=r"(r[1]), "=r"(r[2]), "=r"(r[3]) : "r"(addr));
}
__device__ __forceinline__ void mma16816(float* c, const uint32_t* a, const uint32_t* b) {
    asm volatile(
        "mma.sync.aligned.m16n8k16.row.col.f32.f16.f16.f32 "
        "{%0,%1,%2,%3}, {%4,%5,%6,%7}, {%8,%9}, {%0,%1,%2,%3};"
        : "+f"(c[0]), "+f"(c[1]), "+f"(c[2]), "+f"(c[3])
        : "r"(a[0]), "r"(a[1]), "r"(a[2]), "r"(a[3]), "r"(b[0]), "r"(b[1]));
}
__device__ __forceinline__ void cp16(uint32_t sm, const void* g) {
    asm volatile("cp.async.ca.shared.global [%0], [%1], 16;" :: "r"(sm), "l"(g));
}
#define CP_COMMIT() asm volatile("cp.async.commit_group;" ::: "memory")
#define CP_WAIT0()  asm volatile("cp.async.wait_group 0;" ::: "memory")

// ---------------- setup kernel: S (fp16) + W (fp16) ----------------
__global__ void setup_kernel(const float* __restrict__ pos, const float* __restrict__ W) {
    int i = blockIdx.x * 256 + threadIdx.x;
    if (i < Bb * Gg * CP) {
        int c = i % CP;
        int cell = (i / CP) % Gg;
        int b = i / (CP * Gg);
        float s = 0.0f;
        if (c < Cc) {
            float gp0 = (pos[(b * Cc + c) * 2 + 0] + 1.0f) * 4.0f;
            float gp1 = (pos[(b * Cc + c) * 2 + 1] + 1.0f) * 4.0f;
            float lo0 = floorf(gp0), lo1 = floorf(gp1);
            int il0 = min(7, max(0, (int)lo0)), il1 = min(7, max(0, (int)lo1));
            int ih0 = min(7, max(0, (int)ceilf(gp0))), ih1 = min(7, max(0, (int)ceilf(gp1)));
            float wh0 = gp0 - lo0, wl0 = 1.0f - wh0;
            float wh1 = gp1 - lo1, wl1 = 1.0f - wh1;
            if (il0 * 8 + il1 == cell) s += wl0 * wl1;
            if (il0 * 8 + ih1 == cell) s += wl0 * wh1;
            if (ih0 * 8 + il1 == cell) s += wh0 * wl1;
            if (ih0 * 8 + ih1 == cell) s += wh0 * wh1;
        }
        d_Sh[i] = __float2half_rn(s);
    } else {
        int j = i - Bb * Gg * CP;
        if (j < MPAD * Gg) {
            float v = (j < Mm * Gg) ? W[j] : 0.0f;
            d_Wh[j] = __float2half_rn(v);
        }
    }
}

// ---------------- fused kernel: fp16 2-pass, 2 CTAs/SM ----------------
// smem layout (bytes):
//   phase 1:  A1 [0, 9216)        S fp16 [64][72]
//             B1 [9216, 44032)    xhi [64][136] +0, xlo +17408
//   phase 2:  GV [0, 34816)       gvhi +0, gvlo +17408   (overlays A1/B1, written post-phase1)
//             W  [34816, 76288)   [288][72] fp16          (overlays B1 tail, staged post-phase1)
#define A1PITCH 72
#define B1PITCH 136
#define GPITCH  136
#define WPITCH  72
#define SM_A1   0
#define SM_B1   9216
#define SM_GV   0
#define SM_W    34816
#define SM_TOTAL 76288

__global__ void __launch_bounds__(NTH, 2)
fused_kernel(const float* __restrict__ x, float* __restrict__ out) {
    extern __shared__ char smem[];
    const uint32_t sb = smem_u32(smem);
    const int tid = threadIdx.x;
    const int wid = tid >> 5;           // 0..7
    const int lane = tid & 31;

    const int t0 = blockIdx.x * TT;
    const int b  = blockIdx.y;

    const int arow = lane & 15;
    const int acol = (lane >> 4) * 8;

    // ======== phase 1: gv[64 x 128] = S_b @ x_tile (fp16, 2-pass) ========
    const int wm1 = wid >> 2;           // 0..1, 32 m-rows
    const int wt1 = wid & 3;            // 0..3, 32 t-cols

    float gacc[2][4][4];
#pragma unroll
    for (int i = 0; i < 2; i++)
#pragma unroll
        for (int j = 0; j < 4; j++)
#pragma unroll
            for (int q = 0; q < 4; q++) gacc[i][j][q] = 0.0f;

    float4 xv[8];
    auto load_X = [&](int c0) {   // c0 = channel offset
#pragma unroll
        for (int it = 0; it < 8; it++) {
            int cg = c0 + wid + 8 * it;
            xv[it] = (cg < Cc)
                ? *(const float4*)(x + ((size_t)(b * Cc + cg)) * Tt + t0 + lane * 4)
                : make_float4(0.f, 0.f, 0.f, 0.f);
        }
    };
    auto cpS = [&](int c0) {
        const __half* base = d_Sh + (size_t)b * Gg * CP + c0;
        uint32_t smA = sb + SM_A1;
#pragma unroll
        for (int it = 0; it < 2; it++) {
            int idx = tid + it * NTH;      // 0..511
            int r = idx >> 3;
            int s = idx & 7;
            cp16(smA + (r * A1PITCH + s * 8) * 2, base + r * CP + s * 8);
        }
    };
    auto stsX = [&]() {
        char* base = smem + SM_B1;
#pragma unroll
        for (int it = 0; it < 8; it++) {
            int r = wid + 8 * it;
            float4 v = xv[it];
            __half2 h0 = __floats2half2_rn(v.x, v.y);
            __half2 h1 = __floats2half2_rn(v.z, v.w);
            __half2 l0 = __floats2half2_rn(v.x - __half2float(__low2half(h0)),
                                           v.y - __half2float(__high2half(h0)));
            __half2 l1 = __floats2half2_rn(v.z - __half2float(__low2half(h1)),
                                           v.w - __half2float(__high2half(h1)));
            uint32_t boff = (r * B1PITCH + lane * 4) * 2;
            *(uint32_t*)(base + boff)             = *(uint32_t*)&h0;
            *(uint32_t*)(base + boff + 4)         = *(uint32_t*)&h1;
            *(uint32_t*)(base + 17408 + boff)     = *(uint32_t*)&l0;
            *(uint32_t*)(base + 17408 + boff + 4) = *(uint32_t*)&l1;
        }
    };
    auto mma1 = [&]() {
        uint32_t baseA = sb + SM_A1;
        uint32_t baseB = sb + SM_B1;
#pragma unroll
        for (int ks = 0; ks < 4; ks++) {
            const int k0 = ks * 16;
            uint32_t ah[2][4];
#pragma unroll
            for (int i = 0; i < 2; i++) {
                uint32_t off = ((wm1 * 32 + i * 16 + arow) * A1PITCH + k0 + acol) * 2;
                ldsm_x4(ah[i], baseA + off);
            }
#pragma unroll
            for (int j2 = 0; j2 < 2; j2++) {
                uint32_t off = ((k0 + arow) * B1PITCH + wt1 * 32 + j2 * 16 + acol) * 2;
                uint32_t bhi[4], blo[4];
                ldsm_x4_t(bhi, baseB + off);
                ldsm_x4_t(blo, baseB + 17408 + off);
#pragma unroll
                for (int jh = 0; jh < 2; jh++) {
                    int j = j2 * 2 + jh;
#pragma unroll
                    for (int i = 0; i < 2; i++) {
                        mma16816(gacc[i][j], ah[i], &bhi[jh * 2]);
                        mma16816(gacc[i][j], ah[i], &blo[jh * 2]);
                    }
                }
            }
        }
    };

    // prologue
    cpS(0); CP_COMMIT();
    load_X(0);
    stsX();
    load_X(64);
    CP_WAIT0();
    __syncthreads();

    for (int kc = 0; kc < 5; kc++) {
        mma1();
        if (kc < 4) {
            __syncthreads();                       // chunk kc ldsm done
            cpS((kc + 1) * 64); CP_COMMIT();
            stsX();                                // x(kc+1) from regs
            if (kc < 3) load_X((kc + 2) * 64);     // flies under next MMA
            CP_WAIT0();
            __syncthreads();
        }
    }
    __syncthreads();                               // last mma1 ldsm done before overlays

    // ======== transition: stage ALL of W (cp.async) overlapped with gv split ========
    {
        uint32_t smW = sb + SM_W;
#pragma unroll
        for (int it = 0; it < 9; it++) {
            int idx = tid + it * NTH;      // 0..2303
            int r = idx >> 3;              // 0..287
            int s = idx & 7;
            cp16(smW + (r * WPITCH + s * 8) * 2, d_Wh + r * Gg + s * 8);
        }
        CP_COMMIT();
    }

    // gv split (fp16 hi/lo) into GV region
#pragma unroll
    for (int i = 0; i < 2; i++) {
        int r0 = wm1 * 32 + i * 16 + (lane >> 2);
        int r1 = r0 + 8;
#pragma unroll
        for (int j = 0; j < 4; j++) {
            int t = wt1 * 32 + j * 8 + (lane & 3) * 2;
            __half2 h0 = __floats2half2_rn(gacc[i][j][0], gacc[i][j][1]);
            __half2 l0 = __floats2half2_rn(gacc[i][j][0] - __half2float(__low2half(h0)),
                                           gacc[i][j][1] - __half2float(__high2half(h0)));
            __half2 h1 = __floats2half2_rn(gacc[i][j][2], gacc[i][j][3]);
            __half2 l1 = __floats2half2_rn(gacc[i][j][2] - __half2float(__low2half(h1)),
                                           gacc[i][j][3] - __half2float(__high2half(h1)));
            *(uint32_t*)(smem + SM_GV + (r0 * GPITCH + t) * 2)         = *(uint32_t*)&h0;
            *(uint32_t*)(smem + SM_GV + 17408 + (r0 * GPITCH + t) * 2) = *(uint32_t*)&l0;
            *(uint32_t*)(smem + SM_GV + (r1 * GPITCH + t) * 2)         = *(uint32_t*)&h1;
            *(uint32_t*)(smem + SM_GV + 17408 + (r1 * GPITCH + t) * 2) = *(uint32_t*)&l1;
        }
    }
    CP_WAIT0();
    __syncthreads();

    // ======== phase 2: out = W @ gv (fp16 2-pass), NO internal barriers ========
    const int wm2 = wid >> 2;           // 0..1, 48 m-rows
    const int wt2 = wid & 3;            // 0..3, 32 t-cols

#pragma unroll 1
    for (int mc = 0; mc < 3; mc++) {
        const int m0 = mc * 96;
        float acc[3][4][4];
#pragma unroll
        for (int i = 0; i < 3; i++)
#pragma unroll
            for (int j = 0; j < 4; j++)
#pragma unroll
                for (int q = 0; q < 4; q++) acc[i][j][q] = 0.0f;

#pragma unroll
        for (int ks = 0; ks < 4; ks++) {
            const int k0 = ks * 16;
            uint32_t ah[3][4];
#pragma unroll
            for (int i = 0; i < 3; i++) {
                uint32_t off = ((m0 + wm2 * 48 + i * 16 + arow) * WPITCH + k0 + acol) * 2;
                ldsm_x4(ah[i], sb + SM_W + off);
            }
#pragma unroll
            for (int j2 = 0; j2 < 2; j2++) {
                uint32_t off = ((k0 + arow) * GPITCH + wt2 * 32 + j2 * 16 + acol) * 2;
                uint32_t bhi[4], blo[4];
                ldsm_x4_t(bhi, sb + SM_GV + off);
                ldsm_x4_t(blo, sb + SM_GV + 17408 + off);
#pragma unroll
                for (int jh = 0; jh < 2; jh++) {
                    int j = j2 * 2 + jh;
#pragma unroll
                    for (int i = 0; i < 3; i++) {
                        mma16816(acc[i][j], ah[i], &bhi[jh * 2]);
                        mma16816(acc[i][j], ah[i], &blo[jh * 2]);
                    }
                }
            }
        }

        // epilogue: store out chunk
#pragma unroll
        for (int i = 0; i < 3; i++) {
            int mlo = m0 + wm2 * 48 + i * 16 + (lane >> 2);
            int mhi = mlo + 8;
#pragma unroll
            for (int j = 0; j < 4; j++) {
                int t = t0 + wt2 * 32 + j * 8 + (lane & 3) * 2;
                if (mlo < Mm)
                    *(float2*)&out[((size_t)b * Mm + mlo) * Tt + t] =
                        make_float2(acc[i][j][0], acc[i][j][1]);
                if (mhi < Mm)
                    *(float2*)&out[((size_t)b * Mm + mhi) * Tt + t] =
                        make_float2(acc[i][j][2], acc[i][j][3]);
            }
        }
    }
}

// ---------------- launch ----------------
extern "C" void kernel_launch(void* const* d_in, const int* in_sizes, int n_in,
                              void* d_out, int out_size) {
    const float* x   = (const float*)d_in[0];  // [B, C, T]
    const float* pos = (const float*)d_in[1];  // [B, C, 2]
    const float* W   = (const float*)d_in[2];  // [M, G]
    float* out = (float*)d_out;                // [B, M, T]

    cudaFuncSetAttribute(fused_kernel, cudaFuncAttributeMaxDynamicSharedMemorySize, SM_TOTAL);

    const int njobs = Bb * Gg * CP + MPAD * Gg;
    setup_kernel<<<(njobs + 255) / 256, 256>>>(pos, W);
    fused_kernel<<<dim3(Tt / TT, Bb), NTH, SM_TOTAL>>>(x, out);
}

// round 14
// speedup vs baseline: 1.8222x; 1.2492x over previous
#include <cuda_runtime.h>
#include <cuda_fp16.h>
#include <cstdint>

#define Bb 16
#define Cc 306
#define Tt 4096
#define Mm 270
#define Gg 64
#define TT 128            // t-tile per CTA
#define NTH 256

#define A1PITCH 72
#define XPITCH  136
#define GPITCH  136
#define WPITCH  72
// smem layout (bytes):
//   phase 1: S  [0, 46080)      5 chunks x [64][72] fp16 (stride 9216), built in-CTA
//            X0 [46080, 63488)  [64][136] fp16
//            X1 [63488, 80896)
//   phase 2 overlays (written after phase-1 reads complete):
//            GV [0, 17408)      [64][136] fp16
//            W  [17408, 58880)  [288][72] fp16 (rows >= 270 unwritten; stores guarded)
#define SM_S    0
#define SM_X0   46080
#define SM_X1   63488
#define SM_GV   0
#define SM_W    17408
#define SM_TOTAL 80896

__device__ __forceinline__ uint32_t smem_u32(const void* p) {
    uint32_t a;
    asm("{ .reg .u64 t; cvta.to.shared.u64 t, %1; cvt.u32.u64 %0, t; }" : "=r"(a) : "l"(p));
    return a;
}
__device__ __forceinline__ void ldsm_x4(uint32_t* r, uint32_t addr) {
    asm volatile("ldmatrix.sync.aligned.m8n8.x4.shared.b16 {%0,%1,%2,%3}, [%4];"
                 : "=r"(r[0]), "=r"(r[1]), "=r"(r[2]), "=r"(r[3]) : "r"(addr));
}
__device__ __forceinline__ void ldsm_x4_t(uint32_t* r, uint32_t addr) {
    asm volatile("ldmatrix.sync.aligned.m8n8.x4.trans.shared.b16 {%0,%1,%2,%3}, [%4];"
                 : "=r"(r[0]), "=r"(r[1]), "=r"(r[2]), "=r"(r[3]) : "r"(addr));
}
__device__ __forceinline__ void mma16816(float* c, const uint32_t* a, const uint32_t* b) {
    asm volatile(
        "mma.sync.aligned.m16n8k16.row.col.f32.f16.f16.f32 "
        "{%0,%1,%2,%3}, {%4,%5,%6,%7}, {%8,%9}, {%0,%1,%2,%3};"
        : "+f"(c[0]), "+f"(c[1]), "+f"(c[2]), "+f"(c[3])
        : "r"(a[0]), "r"(a[1]), "r"(a[2]), "r"(a[3]), "r"(b[0]), "r"(b[1]));
}

__global__ void __launch_bounds__(NTH, 2)
fused_kernel(const float* __restrict__ x, const float* __restrict__ pos,
             const float* __restrict__ W, float* __restrict__ out) {
    extern __shared__ char smem[];
    const uint32_t sb = smem_u32(smem);
    const int tid = threadIdx.x;
    const int wid = tid >> 5;           // 0..7
    const int lane = tid & 31;

    const int t0 = blockIdx.x * TT;
    const int b  = blockIdx.y;

    const int arow = lane & 15;
    const int acol = (lane >> 4) * 8;

    // ---- 1. pos loads (issue early) ----
    float2 pA = make_float2(0.f, 0.f), pB = make_float2(0.f, 0.f);
    if (tid < Cc) pA = *(const float2*)(pos + ((size_t)b * Cc + tid) * 2);
    if (tid < Cc - 256) pB = *(const float2*)(pos + ((size_t)b * Cc + 256 + tid) * 2);

    // ---- 2. x chunk0 LDGs (fly under S build) ----
    float4 xv[8];
    auto load_X = [&](int c0) {   // c0 = channel offset
#pragma unroll
        for (int it = 0; it < 8; it++) {
            int cg = c0 + wid + 8 * it;
            xv[it] = (cg < Cc)
                ? *(const float4*)(x + ((size_t)(b * Cc + cg)) * Tt + t0 + lane * 4)
                : make_float4(0.f, 0.f, 0.f, 0.f);
        }
    };
    load_X(0);

    // ---- 3. zero S region (46080 B = 2880 uint4) ----
    {
        uint4 z = make_uint4(0, 0, 0, 0);
#pragma unroll
        for (int it = 0; it < 12; it++) {
            int idx = tid + it * NTH;
            if (idx < 2880) ((uint4*)smem)[idx] = z;
        }
    }
    __syncthreads();   // *** zeroing complete before any scatter write (R13 race fix) ***

    // ---- 4. scatter-build S (fp16) with duplicate-corner merge ----
    auto scat = [&](int c, float2 p) {
        float gp0 = (p.x + 1.0f) * 4.0f;
        float gp1 = (p.y + 1.0f) * 4.0f;
        float f0 = floorf(gp0), f1 = floorf(gp1);
        int il0 = min(7, max(0, (int)f0)), il1 = min(7, max(0, (int)f1));
        int ih0 = min(7, max(0, (int)ceilf(gp0))), ih1 = min(7, max(0, (int)ceilf(gp1)));
        float wh0 = gp0 - f0, wl0 = 1.0f - wh0;
        float wh1 = gp1 - f1, wl1 = 1.0f - wh1;
        float w00 = wl0 * wl1, w01 = wl0 * wh1, w10 = wh0 * wl1, w11 = wh0 * wh1;
        bool d0 = (ih0 == il0), d1 = (ih1 == il1);
        if (d0) { w00 += w10; w01 += w11; }
        if (d1) { w00 += w01; w10 += w11; }
        char* base = smem + SM_S + (c >> 6) * 9216 + (c & 63) * 2;
        *(__half*)(base + (il0 * 8 + il1) * (A1PITCH * 2)) = __float2half_rn(w00);
        if (!d1)        *(__half*)(base + (il0 * 8 + ih1) * (A1PITCH * 2)) = __float2half_rn(w01);
        if (!d0)        *(__half*)(base + (ih0 * 8 + il1) * (A1PITCH * 2)) = __float2half_rn(w10);
        if (!d0 && !d1) *(__half*)(base + (ih0 * 8 + ih1) * (A1PITCH * 2)) = __float2half_rn(w11);
    };
    if (tid < Cc) scat(tid, pA);
    if (tid < Cc - 256) scat(tid + 256, pB);

    // ---- 5. stage x chunk0, prefetch chunk1 ----
    auto stsX = [&](int buf) {
        char* base = smem + (buf ? SM_X1 : SM_X0);
#pragma unroll
        for (int it = 0; it < 8; it++) {
            int r = wid + 8 * it;
            float4 v = xv[it];
            __half2 h0 = __floats2half2_rn(v.x, v.y);
            __half2 h1 = __floats2half2_rn(v.z, v.w);
            uint32_t boff = (r * XPITCH + lane * 4) * 2;
            *(uint32_t*)(base + boff)     = *(uint32_t*)&h0;
            *(uint32_t*)(base + boff + 4) = *(uint32_t*)&h1;
        }
    };
    stsX(0);
    load_X(64);
    __syncthreads();

    // ======== phase 1: gv[64 x 128] = S_b @ x_tile (single fp16) ========
    const int wm1 = wid >> 2;           // 0..1, 32 m-rows
    const int wt1 = wid & 3;            // 0..3, 32 t-cols

    float gacc[2][4][4];
#pragma unroll
    for (int i = 0; i < 2; i++)
#pragma unroll
        for (int j = 0; j < 4; j++)
#pragma unroll
            for (int q = 0; q < 4; q++) gacc[i][j][q] = 0.0f;

    auto mma1 = [&](int kc, int xb) {
        uint32_t baseA = sb + SM_S + kc * 9216;
        uint32_t baseB = sb + (xb ? SM_X1 : SM_X0);
#pragma unroll
        for (int ks = 0; ks < 4; ks++) {
            const int k0 = ks * 16;
            uint32_t ah[2][4];
#pragma unroll
            for (int i = 0; i < 2; i++) {
                uint32_t off = ((wm1 * 32 + i * 16 + arow) * A1PITCH + k0 + acol) * 2;
                ldsm_x4(ah[i], baseA + off);
            }
#pragma unroll
            for (int j2 = 0; j2 < 2; j2++) {
                uint32_t off = ((k0 + arow) * XPITCH + wt1 * 32 + j2 * 16 + acol) * 2;
                uint32_t bh[4];
                ldsm_x4_t(bh, baseB + off);
#pragma unroll
                for (int jh = 0; jh < 2; jh++) {
                    int j = j2 * 2 + jh;
#pragma unroll
                    for (int i = 0; i < 2; i++)
                        mma16816(gacc[i][j], ah[i], &bh[jh * 2]);
                }
            }
        }
    };

    for (int kc = 0; kc < 5; kc++) {
        mma1(kc, kc & 1);
        if (kc < 4) {
            stsX((kc + 1) & 1);                    // x(kc+1) from regs (other buffer)
            if (kc < 3) load_X((kc + 2) * 64);     // flies under next MMA
            __syncthreads();
        }
    }
    __syncthreads();                               // all phase-1 reads done before overlays

    // ======== transition: gv split (fp16) + W convert into smem ========
    // gv → GV region
    {
        int r0 = wm1 * 32 + (lane >> 2);
#pragma unroll
        for (int i = 0; i < 2; i++) {
            int ra = r0 + i * 16, rb = ra + 8;
#pragma unroll
            for (int j = 0; j < 4; j++) {
                int t = wt1 * 32 + j * 8 + (lane & 3) * 2;
                __half2 h0 = __floats2half2_rn(gacc[i][j][0], gacc[i][j][1]);
                __half2 h1 = __floats2half2_rn(gacc[i][j][2], gacc[i][j][3]);
                *(uint32_t*)(smem + SM_GV + (ra * GPITCH + t) * 2) = *(uint32_t*)&h0;
                *(uint32_t*)(smem + SM_GV + (rb * GPITCH + t) * 2) = *(uint32_t*)&h1;
            }
        }
    }
    // W fp32 → fp16 (270 rows x 64 cols; rows 270..287 left unwritten, stores guarded)
    {
#pragma unroll
        for (int it = 0; it < 17; it++) {
            int idx = tid + it * NTH;      // 0..4351, valid < 4320
            if (idx < Mm * 16) {
                int r = idx >> 4, q = idx & 15;
                float4 v = *(const float4*)(W + r * 64 + q * 4);
                __half2 a = __floats2half2_rn(v.x, v.y);
                __half2 c = __floats2half2_rn(v.z, v.w);
                char* d = smem + SM_W + (r * WPITCH + q * 4) * 2;
                *(uint32_t*)d       = *(uint32_t*)&a;
                *(uint32_t*)(d + 4) = *(uint32_t*)&c;
            }
        }
    }
    __syncthreads();

    // ======== phase 2: out = W @ gv (single fp16), no internal barriers ========
    const int wm2 = wid >> 2;           // 0..1, 48 m-rows
    const int wt2 = wid & 3;            // 0..3, 32 t-cols

#pragma unroll 1
    for (int mc = 0; mc < 3; mc++) {
        const int m0 = mc * 96;
        float acc[3][4][4];
#pragma unroll
        for (int i = 0; i < 3; i++)
#pragma unroll
            for (int j = 0; j < 4; j++)
#pragma unroll
                for (int q = 0; q < 4; q++) acc[i][j][q] = 0.0f;

#pragma unroll
        for (int ks = 0; ks < 4; ks++) {
            const int k0 = ks * 16;
            uint32_t ah[3][4];
#pragma unroll
            for (int i = 0; i < 3; i++) {
                uint32_t off = ((m0 + wm2 * 48 + i * 16 + arow) * WPITCH + k0 + acol) * 2;
                ldsm_x4(ah[i], sb + SM_W + off);
            }
#pragma unroll
            for (int j2 = 0; j2 < 2; j2++) {
                uint32_t off = ((k0 + arow) * GPITCH + wt2 * 32 + j2 * 16 + acol) * 2;
                uint32_t bh[4];
                ldsm_x4_t(bh, sb + SM_GV + off);
#pragma unroll
                for (int jh = 0; jh < 2; jh++) {
                    int j = j2 * 2 + jh;
#pragma unroll
                    for (int i = 0; i < 3; i++)
                        mma16816(acc[i][j], ah[i], &bh[jh * 2]);
                }
            }
        }

        // epilogue: store out chunk
#pragma unroll
        for (int i = 0; i < 3; i++) {
            int mlo = m0 + wm2 * 48 + i * 16 + (lane >> 2);
            int mhi = mlo + 8;
#pragma unroll
            for (int j = 0; j < 4; j++) {
                int t = t0 + wt2 * 32 + j * 8 + (lane & 3) * 2;
                if (mlo < Mm)
                    *(float2*)&out[((size_t)b * Mm + mlo) * Tt + t] =
                        make_float2(acc[i][j][0], acc[i][j][1]);
                if (mhi < Mm)
                    *(float2*)&out[((size_t)b * Mm + mhi) * Tt + t] =
                        make_float2(acc[i][j][2], acc[i][j][3]);
            }
        }
    }
}

// ---------------- launch: single kernel ----------------
extern "C" void kernel_launch(void* const* d_in, const int* in_sizes, int n_in,
                              void* d_out, int out_size) {
    const float* x   = (const float*)d_in[0];  // [B, C, T]
    const float* pos = (const float*)d_in[1];  // [B, C, 2]
    const float* W   = (const float*)d_in[2];  // [M, G]
    float* out = (float*)d_out;                // [B, M, T]

    cudaFuncSetAttribute(fused_kernel, cudaFuncAttributeMaxDynamicSharedMemorySize, SM_TOTAL);
    fused_kernel<<<dim3(Tt / TT, Bb), NTH, SM_TOTAL>>>(x, pos, W, out);
}

// round 15
// speedup vs baseline: 1.9221x; 1.0548x over previous
#include <cuda_runtime.h>
#include <cuda_fp16.h>
#include <cstdint>

#define Bb 16
#define Cc 306
#define Tt 4096
#define Mm 270
#define Gg 64
#define TT 256            // t-tile per CTA
#define NTH 256

#define A1PITCH 72
#define XPITCH  264
#define GPITCH  264
#define WPITCH  72
// smem layout (bytes):
//   phase 1: S  [0, 46080)      5 x [64][72] fp16 (stride 9216; 64-wide k blocks), built in-CTA
//            X0 [46080, 62976)  [32][264] fp16 (one 32-channel chunk)
//            X1 [62976, 79872)
//   phase 2 overlays (after all phase-1 reads):
//            GV [0, 33792)      [64][264] fp16
//            W  [33792, 75264)  [288][72] fp16 (rows >= 270 unwritten; stores guarded)
#define SM_S    0
#define SM_X0   46080
#define SM_X1   62976
#define SM_GV   0
#define SM_W    33792
#define SM_TOTAL 79872

__device__ __forceinline__ uint32_t smem_u32(const void* p) {
    uint32_t a;
    asm("{ .reg .u64 t; cvta.to.shared.u64 t, %1; cvt.u32.u64 %0, t; }" : "=r"(a) : "l"(p));
    return a;
}
__device__ __forceinline__ void ldsm_x4(uint32_t* r, uint32_t addr) {
    asm volatile("ldmatrix.sync.aligned.m8n8.x4.shared.b16 {%0,%1,%2,%3}, [%4];"
                 : "=r"(r[0]), "=r"(r[1]), "=r"(r[2]), "=r"(r[3]) : "r"(addr));
}
__device__ __forceinline__ void ldsm_x4_t(uint32_t* r, uint32_t addr) {
    asm volatile("ldmatrix.sync.aligned.m8n8.x4.trans.shared.b16 {%0,%1,%2,%3}, [%4];"
                 : "=r"(r[0]), "=r"(r[1]), "=r"(r[2]), "=r"(r[3]) : "r"(addr));
}
__device__ __forceinline__ void mma16816(float* c, const uint32_t* a, const uint32_t* b) {
    asm volatile(
        "mma.sync.aligned.m16n8k16.row.col.f32.f16.f16.f32 "
        "{%0,%1,%2,%3}, {%4,%5,%6,%7}, {%8,%9}, {%0,%1,%2,%3};"
        : "+f"(c[0]), "+f"(c[1]), "+f"(c[2]), "+f"(c[3])
        : "r"(a[0]), "r"(a[1]), "r"(a[2]), "r"(a[3]), "r"(b[0]), "r"(b[1]));
}

__global__ void __launch_bounds__(NTH, 2)
fused_kernel(const float* __restrict__ x, const float* __restrict__ pos,
             const float* __restrict__ W, float* __restrict__ out) {
    extern __shared__ char smem[];
    const uint32_t sb = smem_u32(smem);
    const int tid = threadIdx.x;
    const int wid = tid >> 5;           // 0..7
    const int lane = tid & 31;

    const int t0 = blockIdx.x * TT;
    const int b  = blockIdx.y;

    const int arow = lane & 15;
    const int acol = (lane >> 4) * 8;

    // ---- 1. pos loads (issue early) ----
    float2 pA = make_float2(0.f, 0.f), pB = make_float2(0.f, 0.f);
    if (tid < Cc) pA = *(const float2*)(pos + ((size_t)b * Cc + tid) * 2);
    if (tid < Cc - 256) pB = *(const float2*)(pos + ((size_t)b * Cc + 256 + tid) * 2);

    // ---- 2. x chunk0 LDGs (32 channels x 256 t; fly under S build) ----
    float4 xv[8];
    auto load_X = [&](int c0) {   // c0 = channel offset, chunk = 32 channels
#pragma unroll
        for (int it = 0; it < 8; it++) {
            int r = wid * 4 + (it >> 1);          // 0..31
            int cg = c0 + r;
            int half = it & 1;                    // t halves of 128
            xv[it] = (cg < Cc)
                ? *(const float4*)(x + ((size_t)(b * Cc + cg)) * Tt + t0 + half * 128 + lane * 4)
                : make_float4(0.f, 0.f, 0.f, 0.f);
        }
    };
    load_X(0);

    // ---- 3. zero S region (46080 B = 2880 uint4) ----
    {
        uint4 z = make_uint4(0, 0, 0, 0);
#pragma unroll
        for (int it = 0; it < 12; it++) {
            int idx = tid + it * NTH;
            if (idx < 2880) ((uint4*)smem)[idx] = z;
        }
    }
    __syncthreads();   // zeroing complete before any scatter write

    // ---- 4. scatter-build S (fp16) with duplicate-corner merge ----
    auto scat = [&](int c, float2 p) {
        float gp0 = (p.x + 1.0f) * 4.0f;
        float gp1 = (p.y + 1.0f) * 4.0f;
        float f0 = floorf(gp0), f1 = floorf(gp1);
        int il0 = min(7, max(0, (int)f0)), il1 = min(7, max(0, (int)f1));
        int ih0 = min(7, max(0, (int)ceilf(gp0))), ih1 = min(7, max(0, (int)ceilf(gp1)));
        float wh0 = gp0 - f0, wl0 = 1.0f - wh0;
        float wh1 = gp1 - f1, wl1 = 1.0f - wh1;
        float w00 = wl0 * wl1, w01 = wl0 * wh1, w10 = wh0 * wl1, w11 = wh0 * wh1;
        bool d0 = (ih0 == il0), d1 = (ih1 == il1);
        if (d0) { w00 += w10; w01 += w11; }
        if (d1) { w00 += w01; w10 += w11; }
        char* base = smem + SM_S + (c >> 6) * 9216 + (c & 63) * 2;
        *(__half*)(base + (il0 * 8 + il1) * (A1PITCH * 2)) = __float2half_rn(w00);
        if (!d1)        *(__half*)(base + (il0 * 8 + ih1) * (A1PITCH * 2)) = __float2half_rn(w01);
        if (!d0)        *(__half*)(base + (ih0 * 8 + il1) * (A1PITCH * 2)) = __float2half_rn(w10);
        if (!d0 && !d1) *(__half*)(base + (ih0 * 8 + ih1) * (A1PITCH * 2)) = __float2half_rn(w11);
    };
    if (tid < Cc) scat(tid, pA);
    if (tid < Cc - 256) scat(tid + 256, pB);

    // ---- 5. stage x chunk0, prefetch chunk1 ----
    auto stsX = [&](int buf) {
        char* base = smem + (buf ? SM_X1 : SM_X0);
#pragma unroll
        for (int it = 0; it < 8; it++) {
            int r = wid * 4 + (it >> 1);
            int half = it & 1;
            float4 v = xv[it];
            __half2 h0 = __floats2half2_rn(v.x, v.y);
            __half2 h1 = __floats2half2_rn(v.z, v.w);
            uint32_t boff = (r * XPITCH + half * 128 + lane * 4) * 2;
            *(uint32_t*)(base + boff)     = *(uint32_t*)&h0;
            *(uint32_t*)(base + boff + 4) = *(uint32_t*)&h1;
        }
    };
    stsX(0);
    load_X(32);
    __syncthreads();

    // ======== phase 1: gv[64 x 256] = S_b @ x_tile (single fp16) ========
    // 8 warps as 2m x 4t; warp tile 32m x 64t
    const int wm1 = wid >> 2;           // 0..1
    const int wt1 = wid & 3;            // 0..3

    float gacc[2][8][4];
#pragma unroll
    for (int i = 0; i < 2; i++)
#pragma unroll
        for (int j = 0; j < 8; j++)
#pragma unroll
            for (int q = 0; q < 4; q++) gacc[i][j][q] = 0.0f;

    auto mma1 = [&](int kcc, int xb) {   // kcc = 32-wide chunk index (0..9)
        uint32_t baseA = sb + SM_S + (kcc >> 1) * 9216;
        const int kbase = (kcc & 1) * 32;
        uint32_t baseB = sb + (xb ? SM_X1 : SM_X0);
#pragma unroll
        for (int ks = 0; ks < 2; ks++) {
            uint32_t ah[2][4];
#pragma unroll
            for (int i = 0; i < 2; i++) {
                uint32_t off = ((wm1 * 32 + i * 16 + arow) * A1PITCH + kbase + ks * 16 + acol) * 2;
                ldsm_x4(ah[i], baseA + off);
            }
#pragma unroll
            for (int j2 = 0; j2 < 4; j2++) {
                uint32_t off = ((ks * 16 + arow) * XPITCH + wt1 * 64 + j2 * 16 + acol) * 2;
                uint32_t bh[4];
                ldsm_x4_t(bh, baseB + off);
#pragma unroll
                for (int jh = 0; jh < 2; jh++) {
                    int j = j2 * 2 + jh;
#pragma unroll
                    for (int i = 0; i < 2; i++)
                        mma16816(gacc[i][j], ah[i], &bh[jh * 2]);
                }
            }
        }
    };

    for (int kcc = 0; kcc < 10; kcc++) {
        mma1(kcc, kcc & 1);
        if (kcc < 9) {
            stsX((kcc + 1) & 1);                   // x(kcc+1) from regs (other buffer)
            if (kcc < 8) load_X((kcc + 2) * 32);   // flies under next MMA
            __syncthreads();
        }
    }
    __syncthreads();                               // all phase-1 reads done before overlays

    // ======== transition: gv (fp16) + W convert into smem ========
    {
        int r0 = wm1 * 32 + (lane >> 2);
#pragma unroll
        for (int i = 0; i < 2; i++) {
            int ra = r0 + i * 16, rb = ra + 8;
#pragma unroll
            for (int j = 0; j < 8; j++) {
                int t = wt1 * 64 + j * 8 + (lane & 3) * 2;
                __half2 h0 = __floats2half2_rn(gacc[i][j][0], gacc[i][j][1]);
                __half2 h1 = __floats2half2_rn(gacc[i][j][2], gacc[i][j][3]);
                *(uint32_t*)(smem + SM_GV + (ra * GPITCH + t) * 2) = *(uint32_t*)&h0;
                *(uint32_t*)(smem + SM_GV + (rb * GPITCH + t) * 2) = *(uint32_t*)&h1;
            }
        }
    }
    // W fp32 -> fp16 (270 rows x 64 cols; rows >= 270 unwritten, stores guarded)
    {
#pragma unroll
        for (int it = 0; it < 17; it++) {
            int idx = tid + it * NTH;      // valid < 4320
            if (idx < Mm * 16) {
                int r = idx >> 4, q = idx & 15;
                float4 v = *(const float4*)(W + r * 64 + q * 4);
                __half2 a = __floats2half2_rn(v.x, v.y);
                __half2 c = __floats2half2_rn(v.z, v.w);
                char* d = smem + SM_W + (r * WPITCH + q * 4) * 2;
                *(uint32_t*)d       = *(uint32_t*)&a;
                *(uint32_t*)(d + 4) = *(uint32_t*)&c;
            }
        }
    }
    __syncthreads();

    // ======== phase 2: out = W @ gv (single fp16), no internal barriers ========
    // 8 warps as 1m x 8t; warp tile 48m x 32t; 6 m-chunks of 48
    const int wt2 = wid;                // 0..7

#pragma unroll 1
    for (int mc = 0; mc < 6; mc++) {
        const int m0 = mc * 48;
        float acc[3][4][4];
#pragma unroll
        for (int i = 0; i < 3; i++)
#pragma unroll
            for (int j = 0; j < 4; j++)
#pragma unroll
                for (int q = 0; q < 4; q++) acc[i][j][q] = 0.0f;

#pragma unroll
        for (int ks = 0; ks < 4; ks++) {
            const int k0 = ks * 16;
            uint32_t ah[3][4];
#pragma unroll
            for (int i = 0; i < 3; i++) {
                uint32_t off = ((m0 + i * 16 + arow) * WPITCH + k0 + acol) * 2;
                ldsm_x4(ah[i], sb + SM_W + off);
            }
#pragma unroll
            for (int j2 = 0; j2 < 2; j2++) {
                uint32_t off = ((k0 + arow) * GPITCH + wt2 * 32 + j2 * 16 + acol) * 2;
                uint32_t bh[4];
                ldsm_x4_t(bh, sb + SM_GV + off);
#pragma unroll
                for (int jh = 0; jh < 2; jh++) {
                    int j = j2 * 2 + jh;
#pragma unroll
                    for (int i = 0; i < 3; i++)
                        mma16816(acc[i][j], ah[i], &bh[jh * 2]);
                }
            }
        }

        // epilogue: store out chunk
#pragma unroll
        for (int i = 0; i < 3; i++) {
            int mlo = m0 + i * 16 + (lane >> 2);
            int mhi = mlo + 8;
#pragma unroll
            for (int j = 0; j < 4; j++) {
                int t = t0 + wt2 * 32 + j * 8 + (lane & 3) * 2;
                if (mlo < Mm)
                    *(float2*)&out[((size_t)b * Mm + mlo) * Tt + t] =
                        make_float2(acc[i][j][0], acc[i][j][1]);
                if (mhi < Mm)
                    *(float2*)&out[((size_t)b * Mm + mhi) * Tt + t] =
                        make_float2(acc[i][j][2], acc[i][j][3]);
            }
        }
    }
}

// ---------------- launch: single kernel, single wave ----------------
extern "C" void kernel_launch(void* const* d_in, const int* in_sizes, int n_in,
                              void* d_out, int out_size) {
    const float* x   = (const float*)d_in[0];  // [B, C, T]
    const float* pos = (const float*)d_in[1];  // [B, C, 2]
    const float* W   = (const float*)d_in[2];  // [M, G]
    float* out = (float*)d_out;                // [B, M, T]

    cudaFuncSetAttribute(fused_kernel, cudaFuncAttributeMaxDynamicSharedMemorySize, SM_TOTAL);
    fused_kernel<<<dim3(Tt / TT, Bb), NTH, SM_TOTAL>>>(x, pos, W, out);
}